// round 2
// baseline (speedup 1.0000x reference)
#include <cuda_runtime.h>

// Problem-size upper bounds (actual sizes derived from in_sizes at launch).
#define NMAX 100000
#define EMAX 3200000

// Scratch (allocation-free rule: __device__ globals).
__device__ int                  g_is64;           // edge_index dtype flag
__device__ int                  g_deg[NMAX];
__device__ __align__(16) float  g_y[NMAX * 16];   // xw[i] * dinv[i]
__device__ __align__(16) float  g_acc[NMAX * 16]; // sum over in-edges of y[row]

// Index accessor: edge_index buffer viewed as int32 words. If the data is
// int64 (little-endian, values >= 0 and < 2^31), element p's low word is at
// word offset 2*p and the odd words are all zero.
__device__ __forceinline__ int get_idx(const int* __restrict__ ei, long long p, int is64) {
    return is64 ? ei[p * 2] : ei[p];
}

// ---------------------------------------------------------------------------
// K0: detect int32 vs int64 edge_index. int32 random indices in [0,1e5) have
// ~1e-5 chance of any single word being zero; requiring 32 odd words all zero
// makes misdetection probability ~1e-160.
__global__ void k_detect(const int* __restrict__ w) {
    int is64 = 1;
    for (int i = 1; i < 64; i += 2)
        if (w[i] != 0) { is64 = 0; break; }
    g_is64 = is64;
}

// ---------------------------------------------------------------------------
// K1: init deg=1 (self loop) and acc=0.
__global__ void k_init(int n) {
    int i = blockIdx.x * blockDim.x + threadIdx.x;
    if (i < n) g_deg[i] = 1;
    if (i < n * 4)
        reinterpret_cast<float4*>(g_acc)[i] = make_float4(0.f, 0.f, 0.f, 0.f);
}

// ---------------------------------------------------------------------------
// K2: in-degree count over col (targets). Spread-address RED.ADD.
__global__ void k_deg(const int* __restrict__ ei, int E, int n) {
    int e = blockIdx.x * blockDim.x + threadIdx.x;
    if (e >= E) return;
    int is64 = g_is64;
    int c = get_idx(ei, (long long)E + e, is64);
    if ((unsigned)c < (unsigned)n) atomicAdd(&g_deg[c], 1);
}

// ---------------------------------------------------------------------------
// K3: y[i][:] = (x[i] @ Wg) * rsqrt(deg[i]).  Wg (512x16 = 32KB) in smem,
// one node per thread, x row streamed as float4 (L1 keeps lines hot).
__global__ void k_gemm(const float* __restrict__ x, const float* __restrict__ Wg, int n) {
    __shared__ float Ws[512 * 16];
    for (int t = threadIdx.x; t < (512 * 16) / 4; t += blockDim.x)
        reinterpret_cast<float4*>(Ws)[t] = reinterpret_cast<const float4*>(Wg)[t];
    __syncthreads();

    int i = blockIdx.x * blockDim.x + threadIdx.x;
    if (i >= n) return;

    float acc[16];
#pragma unroll
    for (int j = 0; j < 16; j++) acc[j] = 0.f;

    const float4* xr = reinterpret_cast<const float4*>(x) + (size_t)i * 128;
#pragma unroll 4
    for (int k4 = 0; k4 < 128; k4++) {
        float4 xv = __ldg(xr + k4);
        const float* w0 = Ws + k4 * 64;  // rows 4*k4 .. 4*k4+3 of Wg
#pragma unroll
        for (int j = 0; j < 16; j++) {
            acc[j] += xv.x * w0[j]
                    + xv.y * w0[16 + j]
                    + xv.z * w0[32 + j]
                    + xv.w * w0[48 + j];
        }
    }

    float di = rsqrtf((float)g_deg[i]);
    float4* yo = reinterpret_cast<float4*>(g_y) + (size_t)i * 4;
#pragma unroll
    for (int q = 0; q < 4; q++)
        yo[q] = make_float4(acc[q * 4 + 0] * di, acc[q * 4 + 1] * di,
                            acc[q * 4 + 2] * di, acc[q * 4 + 3] * di);
}

// ---------------------------------------------------------------------------
// K4: edge scatter. acc[col] += y[row] via vectorized L2 reductions (no return).
__device__ __forceinline__ void red_add_v4(float* addr, float4 v) {
    asm volatile("red.global.add.v4.f32 [%0], {%1, %2, %3, %4};"
                 :: "l"(addr), "f"(v.x), "f"(v.y), "f"(v.z), "f"(v.w)
                 : "memory");
}

__global__ void k_scatter(const int* __restrict__ ei, int E, int n) {
    int e = blockIdx.x * blockDim.x + threadIdx.x;
    if (e >= E) return;
    int is64 = g_is64;
    int r = get_idx(ei, (long long)e, is64);
    int c = get_idx(ei, (long long)E + e, is64);
    if ((unsigned)r >= (unsigned)n || (unsigned)c >= (unsigned)n) return;
    const float4* ys = reinterpret_cast<const float4*>(g_y) + (size_t)r * 4;
    float*       dst = g_acc + (size_t)c * 16;
    float4 v0 = __ldg(ys + 0);
    float4 v1 = __ldg(ys + 1);
    float4 v2 = __ldg(ys + 2);
    float4 v3 = __ldg(ys + 3);
    red_add_v4(dst + 0,  v0);
    red_add_v4(dst + 4,  v1);
    red_add_v4(dst + 8,  v2);
    red_add_v4(dst + 12, v3);
}

// ---------------------------------------------------------------------------
// K5: finalize GCN layer + 3-layer MLP + sigmoid, one node per thread.
__global__ void k_final(const float* __restrict__ bg,
                        const float* __restrict__ W1, const float* __restrict__ b1,
                        const float* __restrict__ W2, const float* __restrict__ b2,
                        const float* __restrict__ W3, const float* __restrict__ b3,
                        float* __restrict__ out, int n) {
    __shared__ float sW1[256], sW2[512], sW3[32];
    __shared__ float sbg[16], sb1[16], sb2[32], sb3;
    int t = threadIdx.x;
    if (t < 256) sW1[t] = W1[t];
    for (int q = t; q < 512; q += blockDim.x) sW2[q] = W2[q];
    if (t < 32) { sW3[t] = W3[t]; sb2[t] = b2[t]; }
    if (t < 16) { sb1[t] = b1[t]; sbg[t] = bg[t]; }
    if (t == 0) sb3 = b3[0];
    __syncthreads();

    int i = blockIdx.x * blockDim.x + t;
    if (i >= n) return;

    float di = rsqrtf((float)g_deg[i]);
    const float4* ar = reinterpret_cast<const float4*>(g_acc) + (size_t)i * 4;
    const float4* yr = reinterpret_cast<const float4*>(g_y) + (size_t)i * 4;

    float h0[16];
#pragma unroll
    for (int q = 0; q < 4; q++) {
        float4 a = ar[q];
        float4 y = yr[q];
        h0[q * 4 + 0] = fmaxf((a.x + y.x) * di + sbg[q * 4 + 0], 0.f);
        h0[q * 4 + 1] = fmaxf((a.y + y.y) * di + sbg[q * 4 + 1], 0.f);
        h0[q * 4 + 2] = fmaxf((a.z + y.z) * di + sbg[q * 4 + 2], 0.f);
        h0[q * 4 + 3] = fmaxf((a.w + y.w) * di + sbg[q * 4 + 3], 0.f);
    }

    float h1[16];
#pragma unroll
    for (int j = 0; j < 16; j++) {
        float s = sb1[j];
#pragma unroll
        for (int k = 0; k < 16; k++) s += h0[k] * sW1[k * 16 + j];
        h1[j] = fmaxf(s, 0.f);
    }

    float z = sb3;
#pragma unroll
    for (int j = 0; j < 32; j++) {
        float s = sb2[j];
#pragma unroll
        for (int k = 0; k < 16; k++) s += h1[k] * sW2[k * 32 + j];
        z += fmaxf(s, 0.f) * sW3[j];
    }

    out[i] = 1.f / (1.f + expf(-z));
}

// ---------------------------------------------------------------------------
extern "C" void kernel_launch(void* const* d_in, const int* in_sizes, int n_in,
                              void* d_out, int out_size) {
    const float* x  = (const float*)d_in[0];
    const int*   ei = (const int*)d_in[1];   // edge_index words (int32 or int64 LE)
    const float* Wg = (const float*)d_in[2];
    const float* bg = (const float*)d_in[3];
    const float* W1 = (const float*)d_in[4];
    const float* b1 = (const float*)d_in[5];
    const float* W2 = (const float*)d_in[6];
    const float* b2 = (const float*)d_in[7];
    const float* W3 = (const float*)d_in[8];
    const float* b3 = (const float*)d_in[9];
    float* out = (float*)d_out;

    int n = in_sizes[0] / 512;
    int E = in_sizes[1] / 2;   // element count, dtype-independent
    if (n > NMAX) n = NMAX;
    if (E > EMAX) E = EMAX;

    k_detect <<<1, 1>>>(ei);
    k_init   <<<(n * 4 + 255) / 256, 256>>>(n);
    k_deg    <<<(E + 255) / 256, 256>>>(ei, E, n);
    k_gemm   <<<(n + 127) / 128, 128>>>(x, Wg, n);
    k_scatter<<<(E + 255) / 256, 256>>>(ei, E, n);
    k_final  <<<(n + 255) / 256, 256>>>(bg, W1, b1, W2, b2, W3, b3, out, n);
}

// round 4
// speedup vs baseline: 1.2676x; 1.2676x over previous
#include <cuda_runtime.h>
#include <cstdint>

// Problem-size upper bounds (actual sizes derived from in_sizes at launch).
#define NMAX 100000
#define EMAX 3200000

// GEMM tiling
#define BLK   128   // threads per block
#define NPT   2     // nodes per thread
#define NPB   256   // nodes per block (BLK*NPT)
#define KC    32    // K-chunk
#define XS    36    // padded row stride in smem (floats)
#define NCHUNK 16   // 512 / KC

// Scratch (allocation-free rule: __device__ globals).
__device__ int                  g_is64;           // edge_index dtype flag
__device__ int                  g_deg[NMAX];
__device__ __align__(16) float  g_y[NMAX * 16];   // xw[i] * dinv[i]
__device__ __align__(16) float  g_acc[NMAX * 16]; // sum over in-edges of y[row]

__device__ __forceinline__ int get_idx(const int* __restrict__ ei, long long p, int is64) {
    return is64 ? ei[p * 2] : ei[p];
}

// ---------------------------------------------------------------------------
// K0: detect int32 vs int64 edge_index (odd words all zero => int64 LE).
__global__ void k_detect(const int* __restrict__ w) {
    int is64 = 1;
    for (int i = 1; i < 64; i += 2)
        if (w[i] != 0) { is64 = 0; break; }
    g_is64 = is64;
}

// ---------------------------------------------------------------------------
// K1: init deg=1 (self loop) and acc=0.
__global__ void k_init(int n) {
    int i = blockIdx.x * blockDim.x + threadIdx.x;
    if (i < n) g_deg[i] = 1;
    if (i < n * 4)
        reinterpret_cast<float4*>(g_acc)[i] = make_float4(0.f, 0.f, 0.f, 0.f);
}

// ---------------------------------------------------------------------------
// K2: in-degree count over col (targets).
__global__ void k_deg(const int* __restrict__ ei, int E, int n) {
    int e = blockIdx.x * blockDim.x + threadIdx.x;
    if (e >= E) return;
    int is64 = g_is64;
    int c = get_idx(ei, (long long)E + e, is64);
    if ((unsigned)c < (unsigned)n) atomicAdd(&g_deg[c], 1);
}

// ---------------------------------------------------------------------------
// K3: y = (x @ Wg) * dinv.  Tiled: 256 nodes/block, cp.async double-buffered
// x tiles (coalesced), Wg in smem (broadcast reads), 2 nodes/thread.
__device__ __forceinline__ void cp_async16(unsigned int sa, const void* ga) {
    asm volatile("cp.async.cg.shared.global [%0], [%1], 16;" :: "r"(sa), "l"(ga));
}

__device__ __forceinline__ void issue_chunk(float* xs, const float* __restrict__ x,
                                            int node0, int n, int c, int buf, int tid) {
    // 256 rows x 32 floats (128B/row) = 2048 float4; 16 per thread.
    unsigned int sbase = (unsigned int)__cvta_generic_to_shared(xs)
                       + (unsigned int)buf * (NPB * XS * 4);
#pragma unroll
    for (int i = 0; i < 16; i++) {
        int idx  = tid + i * BLK;
        int row  = idx >> 3;         // 0..255
        int q    = idx & 7;          // float4 within 128B row-chunk
        int gr   = node0 + row;
        if (gr >= n) gr = n - 1;     // clamp (results discarded on write)
        const void* ga = x + (size_t)gr * 512 + c * KC + q * 4;
        cp_async16(sbase + (unsigned int)(row * XS + q * 4) * 4, ga);
    }
    asm volatile("cp.async.commit_group;" ::: "memory");
}

__global__ void __launch_bounds__(BLK) k_gemm(const float* __restrict__ x,
                                              const float* __restrict__ Wg, int n) {
    extern __shared__ float sm[];
    float* Ws = sm;            // 512*16 floats = 32KB
    float* xs = sm + 512 * 16; // 2 * 256 * 36 floats

    int tid = threadIdx.x;
    int node0 = blockIdx.x * NPB;

    for (int i = tid; i < (512 * 16) / 4; i += BLK)
        reinterpret_cast<float4*>(Ws)[i] = reinterpret_cast<const float4*>(Wg)[i];

    issue_chunk(xs, x, node0, n, 0, 0, tid);

    float acc0[16], acc1[16];
#pragma unroll
    for (int j = 0; j < 16; j++) { acc0[j] = 0.f; acc1[j] = 0.f; }

    for (int c = 0; c < NCHUNK; c++) {
        int buf = c & 1;
        if (c + 1 < NCHUNK) {
            issue_chunk(xs, x, node0, n, c + 1, buf ^ 1, tid);
            asm volatile("cp.async.wait_group 1;" ::: "memory");
        } else {
            asm volatile("cp.async.wait_group 0;" ::: "memory");
        }
        __syncthreads();

        const float* xr0 = xs + buf * (NPB * XS) + tid * XS;
        const float* xr1 = xr0 + BLK * XS;
#pragma unroll
        for (int k4 = 0; k4 < KC / 4; k4++) {
            float4 a = *reinterpret_cast<const float4*>(xr0 + k4 * 4);
            float4 b = *reinterpret_cast<const float4*>(xr1 + k4 * 4);
            const float* xa = &a.x;
            const float* xb = &b.x;
#pragma unroll
            for (int d = 0; d < 4; d++) {
                const float* w = Ws + (c * KC + k4 * 4 + d) * 16;
                float xv0 = xa[d], xv1 = xb[d];
#pragma unroll
                for (int j = 0; j < 16; j++) {
                    acc0[j] += xv0 * w[j];
                    acc1[j] += xv1 * w[j];
                }
            }
        }
        __syncthreads();  // tile consumed before next prefetch overwrites it
    }

    int i0 = node0 + tid;
    int i1 = i0 + BLK;
    if (i0 < n) {
        float di = rsqrtf((float)g_deg[i0]);
        float4* yo = reinterpret_cast<float4*>(g_y) + (size_t)i0 * 4;
#pragma unroll
        for (int q = 0; q < 4; q++)
            yo[q] = make_float4(acc0[q * 4 + 0] * di, acc0[q * 4 + 1] * di,
                                acc0[q * 4 + 2] * di, acc0[q * 4 + 3] * di);
    }
    if (i1 < n) {
        float di = rsqrtf((float)g_deg[i1]);
        float4* yo = reinterpret_cast<float4*>(g_y) + (size_t)i1 * 4;
#pragma unroll
        for (int q = 0; q < 4; q++)
            yo[q] = make_float4(acc1[q * 4 + 0] * di, acc1[q * 4 + 1] * di,
                                acc1[q * 4 + 2] * di, acc1[q * 4 + 3] * di);
    }
}

// ---------------------------------------------------------------------------
// K4: edge scatter. acc[col] += y[row] via vectorized L2 reductions.
__device__ __forceinline__ void red_add_v4(float* addr, float4 v) {
    asm volatile("red.global.add.v4.f32 [%0], {%1, %2, %3, %4};"
                 :: "l"(addr), "f"(v.x), "f"(v.y), "f"(v.z), "f"(v.w)
                 : "memory");
}

__global__ void k_scatter(const int* __restrict__ ei, int E, int n) {
    int e = blockIdx.x * blockDim.x + threadIdx.x;
    if (e >= E) return;
    int is64 = g_is64;
    int r = get_idx(ei, (long long)e, is64);
    int c = get_idx(ei, (long long)E + e, is64);
    if ((unsigned)r >= (unsigned)n || (unsigned)c >= (unsigned)n) return;
    const float4* ys = reinterpret_cast<const float4*>(g_y) + (size_t)r * 4;
    float*       dst = g_acc + (size_t)c * 16;
    float4 v0 = __ldg(ys + 0);
    float4 v1 = __ldg(ys + 1);
    float4 v2 = __ldg(ys + 2);
    float4 v3 = __ldg(ys + 3);
    red_add_v4(dst + 0,  v0);
    red_add_v4(dst + 4,  v1);
    red_add_v4(dst + 8,  v2);
    red_add_v4(dst + 12, v3);
}

// ---------------------------------------------------------------------------
// K5: finalize GCN layer + 3-layer MLP + sigmoid.
__global__ void k_final(const float* __restrict__ bg,
                        const float* __restrict__ W1, const float* __restrict__ b1,
                        const float* __restrict__ W2, const float* __restrict__ b2,
                        const float* __restrict__ W3, const float* __restrict__ b3,
                        float* __restrict__ out, int n) {
    __shared__ float sW1[256], sW2[512], sW3[32];
    __shared__ float sbg[16], sb1[16], sb2[32], sb3;
    int t = threadIdx.x;
    if (t < 256) sW1[t] = W1[t];
    for (int q = t; q < 512; q += blockDim.x) sW2[q] = W2[q];
    if (t < 32) { sW3[t] = W3[t]; sb2[t] = b2[t]; }
    if (t < 16) { sb1[t] = b1[t]; sbg[t] = bg[t]; }
    if (t == 0) sb3 = b3[0];
    __syncthreads();

    int i = blockIdx.x * blockDim.x + t;
    if (i >= n) return;

    float di = rsqrtf((float)g_deg[i]);
    const float4* ar = reinterpret_cast<const float4*>(g_acc) + (size_t)i * 4;
    const float4* yr = reinterpret_cast<const float4*>(g_y) + (size_t)i * 4;

    float h0[16];
#pragma unroll
    for (int q = 0; q < 4; q++) {
        float4 a = ar[q];
        float4 y = yr[q];
        h0[q * 4 + 0] = fmaxf((a.x + y.x) * di + sbg[q * 4 + 0], 0.f);
        h0[q * 4 + 1] = fmaxf((a.y + y.y) * di + sbg[q * 4 + 1], 0.f);
        h0[q * 4 + 2] = fmaxf((a.z + y.z) * di + sbg[q * 4 + 2], 0.f);
        h0[q * 4 + 3] = fmaxf((a.w + y.w) * di + sbg[q * 4 + 3], 0.f);
    }

    float h1[16];
#pragma unroll
    for (int j = 0; j < 16; j++) {
        float s = sb1[j];
#pragma unroll
        for (int k = 0; k < 16; k++) s += h0[k] * sW1[k * 16 + j];
        h1[j] = fmaxf(s, 0.f);
    }

    float z = sb3;
#pragma unroll
    for (int j = 0; j < 32; j++) {
        float s = sb2[j];
#pragma unroll
        for (int k = 0; k < 16; k++) s += h1[k] * sW2[k * 32 + j];
        z += fmaxf(s, 0.f) * sW3[j];
    }

    out[i] = 1.f / (1.f + expf(-z));
}

// ---------------------------------------------------------------------------
extern "C" void kernel_launch(void* const* d_in, const int* in_sizes, int n_in,
                              void* d_out, int out_size) {
    const float* x  = (const float*)d_in[0];
    const int*   ei = (const int*)d_in[1];   // edge_index words (int32 or int64 LE)
    const float* Wg = (const float*)d_in[2];
    const float* bg = (const float*)d_in[3];
    const float* W1 = (const float*)d_in[4];
    const float* b1 = (const float*)d_in[5];
    const float* W2 = (const float*)d_in[6];
    const float* b2 = (const float*)d_in[7];
    const float* W3 = (const float*)d_in[8];
    const float* b3 = (const float*)d_in[9];
    float* out = (float*)d_out;

    int n = in_sizes[0] / 512;
    int E = in_sizes[1] / 2;   // element count, dtype-independent
    if (n > NMAX) n = NMAX;
    if (E > EMAX) E = EMAX;

    static int smem_set = 0;
    int gemm_smem = (512 * 16 + 2 * NPB * XS) * 4;  // 32KB + 72KB = 104KB
    if (!smem_set) {
        cudaFuncSetAttribute(k_gemm, cudaFuncAttributeMaxDynamicSharedMemorySize, gemm_smem);
        smem_set = 1;
    }

    k_detect <<<1, 1>>>(ei);
    k_init   <<<(n * 4 + 255) / 256, 256>>>(n);
    k_deg    <<<(E + 255) / 256, 256>>>(ei, E, n);
    k_gemm   <<<(n + NPB - 1) / NPB, BLK, gemm_smem>>>(x, Wg, n);
    k_scatter<<<(E + 255) / 256, 256>>>(ei, E, n);
    k_final  <<<(n + 255) / 256, 256>>>(bg, W1, b1, W2, b2, W3, b3, out, n);
}

// round 6
// speedup vs baseline: 1.3882x; 1.0952x over previous
#include <cuda_runtime.h>
#include <cstdint>

// Problem-size upper bounds (actual sizes derived from in_sizes at launch).
#define NMAX 100000
#define EMAX 3200000

// GEMM tiling
#define BLK   256   // threads per block
#define NPB   512   // nodes per block (2 per thread)
#define KC    16    // K-chunk (floats per row per chunk)
#define NCH   32    // 512 / KC

// Scratch (allocation-free rule: __device__ globals).
__device__ int                  g_is64;           // edge_index dtype flag
__device__ int                  g_deg[NMAX];
__device__ __align__(16) float  g_y[NMAX * 16];   // xw[i] * dinv[i]
__device__ __align__(16) float  g_acc[NMAX * 16]; // sum over in-edges of y[row]

__device__ __forceinline__ int get_idx(const int* __restrict__ ei, long long p, int is64) {
    return is64 ? ei[p * 2] : ei[p];
}

// f32x2 packed-FMA helpers (Blackwell dual-FMA pipe; PTX-only).
__device__ __forceinline__ unsigned long long pk2(float v) {
    unsigned long long r;
    asm("mov.b64 %0, {%1, %1};" : "=l"(r) : "f"(v));
    return r;
}
__device__ __forceinline__ unsigned long long fma2(unsigned long long a,
                                                   unsigned long long b,
                                                   unsigned long long c) {
    unsigned long long d;
    asm("fma.rn.f32x2 %0, %1, %2, %3;" : "=l"(d) : "l"(a), "l"(b), "l"(c));
    return d;
}
__device__ __forceinline__ unsigned long long mul2(unsigned long long a,
                                                   unsigned long long b) {
    unsigned long long d;
    asm("mul.rn.f32x2 %0, %1, %2;" : "=l"(d) : "l"(a), "l"(b));
    return d;
}

// ---------------------------------------------------------------------------
// K0: detect int32 vs int64 edge_index (odd words all zero => int64 LE).
__global__ void k_detect(const int* __restrict__ w) {
    int is64 = 1;
    for (int i = 1; i < 64; i += 2)
        if (w[i] != 0) { is64 = 0; break; }
    g_is64 = is64;
}

// ---------------------------------------------------------------------------
// K1: init deg=1 (self loop) and acc=0.
__global__ void k_init(int n) {
    int i = blockIdx.x * blockDim.x + threadIdx.x;
    if (i < n) g_deg[i] = 1;
    if (i < n * 4)
        reinterpret_cast<float4*>(g_acc)[i] = make_float4(0.f, 0.f, 0.f, 0.f);
}

// ---------------------------------------------------------------------------
// K2: in-degree count over col (targets).
__global__ void k_deg(const int* __restrict__ ei, int E, int n) {
    int e = blockIdx.x * blockDim.x + threadIdx.x;
    if (e >= E) return;
    int is64 = g_is64;
    int c = get_idx(ei, (long long)E + e, is64);
    if ((unsigned)c < (unsigned)n) atomicAdd(&g_deg[c], 1);
}

// ---------------------------------------------------------------------------
// K3: y = (x @ Wg) * dinv. 512 nodes/block, cp.async double-buffered x tiles,
// XOR-swizzled smem layout (conflict-free LDS.128), f32x2 packed FMAs.
__device__ __forceinline__ void cp_async16(unsigned int sa, const void* ga) {
    asm volatile("cp.async.cg.shared.global [%0], [%1], 16;" :: "r"(sa), "l"(ga));
}

// Swizzle: float4 q of row r lives at byte offset r*64 + ((q ^ ((r>>1)&3))<<4).
// Over any 8 consecutive rows, (r&1, (r>>1)&3) covers all eight 16B slots of
// the 128B bank window -> conflict-free LDS.128; dst stays 16B aligned.
__device__ __forceinline__ void issue_chunk(float* xs, const float* __restrict__ x,
                                            int node0, int n, int c, int buf, int tid) {
    unsigned int sbase = (unsigned int)__cvta_generic_to_shared(xs)
                       + (unsigned int)buf * (NPB * KC * 4);
#pragma unroll
    for (int i = 0; i < 8; i++) {
        int idx = tid + i * BLK;        // 0..2047
        int row = idx >> 2;             // 0..511
        int q   = idx & 3;
        int gr  = node0 + row;
        if (gr >= n) gr = n - 1;        // clamp (results discarded on write)
        const void* ga = x + (size_t)gr * 512 + c * KC + q * 4;
        unsigned int off = (unsigned int)(row * 64 + ((q ^ ((row >> 1) & 3)) << 4));
        cp_async16(sbase + off, ga);
    }
    asm volatile("cp.async.commit_group;" ::: "memory");
}

__global__ void __launch_bounds__(BLK, 2) k_gemm(const float* __restrict__ x,
                                                 const float* __restrict__ Wg, int n) {
    extern __shared__ float sm[];
    float* Ws = sm;             // 512*16 floats = 32KB
    float* xs = sm + 512 * 16;  // 2 * 512 * 16 floats = 64KB

    int tid = threadIdx.x;
    int node0 = blockIdx.x * NPB;

    for (int i = tid; i < (512 * 16) / 4; i += BLK)
        reinterpret_cast<float4*>(Ws)[i] = reinterpret_cast<const float4*>(Wg)[i];

    issue_chunk(xs, x, node0, n, 0, 0, tid);

    unsigned long long acc0[8], acc1[8];
    unsigned long long z = pk2(0.f);
#pragma unroll
    for (int j = 0; j < 8; j++) { acc0[j] = z; acc1[j] = z; }

    int swz = (tid >> 1) & 3;  // same for row tid and tid+256

    for (int c = 0; c < NCH; c++) {
        int buf = c & 1;
        if (c + 1 < NCH) {
            issue_chunk(xs, x, node0, n, c + 1, buf ^ 1, tid);
            asm volatile("cp.async.wait_group 1;" ::: "memory");
        } else {
            asm volatile("cp.async.wait_group 0;" ::: "memory");
        }
        __syncthreads();

        const float* bb = xs + buf * (NPB * KC);
#pragma unroll
        for (int k4 = 0; k4 < 4; k4++) {
            int qq = k4 ^ swz;
            float4 a  = *reinterpret_cast<const float4*>(bb + tid * 16 + qq * 4);
            float4 b4 = *reinterpret_cast<const float4*>(bb + (tid + 256) * 16 + qq * 4);
            const float* xa = &a.x;
            const float* xb = &b4.x;
#pragma unroll
            for (int d = 0; d < 4; d++) {
                int k = c * KC + k4 * 4 + d;
                const unsigned long long* w2 =
                    reinterpret_cast<const unsigned long long*>(Ws + k * 16);
                unsigned long long xv0 = pk2(xa[d]);
                unsigned long long xv1 = pk2(xb[d]);
#pragma unroll
                for (int j = 0; j < 8; j++) {
                    acc0[j] = fma2(xv0, w2[j], acc0[j]);
                    acc1[j] = fma2(xv1, w2[j], acc1[j]);
                }
            }
        }
        __syncthreads();  // tile consumed before next prefetch overwrites it
    }

    int i0 = node0 + tid;
    int i1 = i0 + 256;
    if (i0 < n) {
        unsigned long long dd = pk2(rsqrtf((float)g_deg[i0]));
        unsigned long long* yo = reinterpret_cast<unsigned long long*>(g_y + (size_t)i0 * 16);
#pragma unroll
        for (int j = 0; j < 8; j++) yo[j] = mul2(acc0[j], dd);
    }
    if (i1 < n) {
        unsigned long long dd = pk2(rsqrtf((float)g_deg[i1]));
        unsigned long long* yo = reinterpret_cast<unsigned long long*>(g_y + (size_t)i1 * 16);
#pragma unroll
        for (int j = 0; j < 8; j++) yo[j] = mul2(acc1[j], dd);
    }
}

// ---------------------------------------------------------------------------
// K4: edge scatter. acc[col] += y[row] via vectorized L2 reductions.
__device__ __forceinline__ void red_add_v4(float* addr, float4 v) {
    asm volatile("red.global.add.v4.f32 [%0], {%1, %2, %3, %4};"
                 :: "l"(addr), "f"(v.x), "f"(v.y), "f"(v.z), "f"(v.w)
                 : "memory");
}

__global__ void k_scatter(const int* __restrict__ ei, int E, int n) {
    int e = blockIdx.x * blockDim.x + threadIdx.x;
    if (e >= E) return;
    int is64 = g_is64;
    int r = get_idx(ei, (long long)e, is64);
    int c = get_idx(ei, (long long)E + e, is64);
    if ((unsigned)r >= (unsigned)n || (unsigned)c >= (unsigned)n) return;
    const float4* ys = reinterpret_cast<const float4*>(g_y) + (size_t)r * 4;
    float*       dst = g_acc + (size_t)c * 16;
    float4 v0 = __ldg(ys + 0);
    float4 v1 = __ldg(ys + 1);
    float4 v2 = __ldg(ys + 2);
    float4 v3 = __ldg(ys + 3);
    red_add_v4(dst + 0,  v0);
    red_add_v4(dst + 4,  v1);
    red_add_v4(dst + 8,  v2);
    red_add_v4(dst + 12, v3);
}

// ---------------------------------------------------------------------------
// K5: finalize GCN layer + 3-layer MLP + sigmoid.
__global__ void k_final(const float* __restrict__ bg,
                        const float* __restrict__ W1, const float* __restrict__ b1,
                        const float* __restrict__ W2, const float* __restrict__ b2,
                        const float* __restrict__ W3, const float* __restrict__ b3,
                        float* __restrict__ out, int n) {
    __shared__ float sW1[256], sW2[512], sW3[32];
    __shared__ float sbg[16], sb1[16], sb2[32], sb3;
    int t = threadIdx.x;
    if (t < 256) sW1[t] = W1[t];
    for (int q = t; q < 512; q += blockDim.x) sW2[q] = W2[q];
    if (t < 32) { sW3[t] = W3[t]; sb2[t] = b2[t]; }
    if (t < 16) { sb1[t] = b1[t]; sbg[t] = bg[t]; }
    if (t == 0) sb3 = b3[0];
    __syncthreads();

    int i = blockIdx.x * blockDim.x + t;
    if (i >= n) return;

    float di = rsqrtf((float)g_deg[i]);
    const float4* ar = reinterpret_cast<const float4*>(g_acc) + (size_t)i * 4;
    const float4* yr = reinterpret_cast<const float4*>(g_y) + (size_t)i * 4;

    float h0[16];
#pragma unroll
    for (int q = 0; q < 4; q++) {
        float4 a = ar[q];
        float4 y = yr[q];
        h0[q * 4 + 0] = fmaxf((a.x + y.x) * di + sbg[q * 4 + 0], 0.f);
        h0[q * 4 + 1] = fmaxf((a.y + y.y) * di + sbg[q * 4 + 1], 0.f);
        h0[q * 4 + 2] = fmaxf((a.z + y.z) * di + sbg[q * 4 + 2], 0.f);
        h0[q * 4 + 3] = fmaxf((a.w + y.w) * di + sbg[q * 4 + 3], 0.f);
    }

    float h1[16];
#pragma unroll
    for (int j = 0; j < 16; j++) {
        float s = sb1[j];
#pragma unroll
        for (int k = 0; k < 16; k++) s += h0[k] * sW1[k * 16 + j];
        h1[j] = fmaxf(s, 0.f);
    }

    float z = sb3;
#pragma unroll
    for (int j = 0; j < 32; j++) {
        float s = sb2[j];
#pragma unroll
        for (int k = 0; k < 16; k++) s += h1[k] * sW2[k * 32 + j];
        z += fmaxf(s, 0.f) * sW3[j];
    }

    out[i] = 1.f / (1.f + expf(-z));
}

// ---------------------------------------------------------------------------
extern "C" void kernel_launch(void* const* d_in, const int* in_sizes, int n_in,
                              void* d_out, int out_size) {
    const float* x  = (const float*)d_in[0];
    const int*   ei = (const int*)d_in[1];   // edge_index words (int32 or int64 LE)
    const float* Wg = (const float*)d_in[2];
    const float* bg = (const float*)d_in[3];
    const float* W1 = (const float*)d_in[4];
    const float* b1 = (const float*)d_in[5];
    const float* W2 = (const float*)d_in[6];
    const float* b2 = (const float*)d_in[7];
    const float* W3 = (const float*)d_in[8];
    const float* b3 = (const float*)d_in[9];
    float* out = (float*)d_out;

    int n = in_sizes[0] / 512;
    int E = in_sizes[1] / 2;   // element count, dtype-independent
    if (n > NMAX) n = NMAX;
    if (E > EMAX) E = EMAX;

    static int smem_set = 0;
    int gemm_smem = (512 * 16 + 2 * NPB * KC) * 4;  // 32KB + 64KB = 96KB
    if (!smem_set) {
        cudaFuncSetAttribute(k_gemm, cudaFuncAttributeMaxDynamicSharedMemorySize, gemm_smem);
        smem_set = 1;
    }

    k_detect <<<1, 1>>>(ei);
    k_init   <<<(n * 4 + 255) / 256, 256>>>(n);
    k_deg    <<<(E + 255) / 256, 256>>>(ei, E, n);
    k_gemm   <<<(n + NPB - 1) / NPB, BLK, gemm_smem>>>(x, Wg, n);
    k_scatter<<<(E + 255) / 256, 256>>>(ei, E, n);
    k_final  <<<(n + 255) / 256, 256>>>(bg, W1, b1, W2, b2, W3, b3, out, n);
}

// round 7
// speedup vs baseline: 1.4520x; 1.0459x over previous
#include <cuda_runtime.h>
#include <cstdint>

// Problem-size upper bounds (actual sizes derived from in_sizes at launch).
#define NMAX 100000
#define EMAX 3200000
#define CAP  128     // bucket capacity per node (random E/N=32; overflow -> list)

// GEMM tiling
#define BLK   128   // threads per block
#define NPB   256   // nodes per block (2 per thread)
#define KC    8     // K-chunk (floats per row per chunk)
#define NCH   64    // 512 / KC
#define NSTG  4     // cp.async pipeline stages

// Scratch (allocation-free rule: __device__ globals).
__device__ int                  g_is64;            // edge_index dtype flag
__device__ int                  g_cnt[NMAX];       // in-degree (excl. self loop)
__device__ float                g_dinv[NMAX];      // rsqrt(cnt+1)
__device__ int                  g_bucket[(size_t)NMAX * CAP];
__device__ int                  g_ovf_cnt;
__device__ int                  g_ovf_r[EMAX];
__device__ int                  g_ovf_c[EMAX];
__device__ __align__(16) float  g_y[NMAX * 16];    // xw[i]
__device__ __align__(16) float  g_acc[NMAX * 16];  // sum_in y[r]*dinv[r]

__device__ __forceinline__ int get_idx(const int* __restrict__ ei, long long p, int is64) {
    return is64 ? ei[p * 2] : ei[p];
}

// f32x2 packed-FMA helpers (Blackwell dual-FMA pipe; PTX-only).
__device__ __forceinline__ unsigned long long pk2(float v) {
    unsigned long long r;
    asm("mov.b64 %0, {%1, %1};" : "=l"(r) : "f"(v));
    return r;
}
__device__ __forceinline__ unsigned long long fma2(unsigned long long a,
                                                   unsigned long long b,
                                                   unsigned long long c) {
    unsigned long long d;
    asm("fma.rn.f32x2 %0, %1, %2, %3;" : "=l"(d) : "l"(a), "l"(b), "l"(c));
    return d;
}

// ---------------------------------------------------------------------------
// K0: detect int32 vs int64 edge_index (odd words all zero => int64 LE).
__global__ void k_detect(const int* __restrict__ w) {
    int is64 = 1;
    for (int i = 1; i < 64; i += 2)
        if (w[i] != 0) { is64 = 0; break; }
    g_is64 = is64;
}

// ---------------------------------------------------------------------------
// K1: zero counters.
__global__ void k_init(int n) {
    int i = blockIdx.x * blockDim.x + threadIdx.x;
    if (i < n) g_cnt[i] = 0;
    if (i == 0) g_ovf_cnt = 0;
}

// ---------------------------------------------------------------------------
// K2: bucket fill. bucket[c][pos] = r; counts in-degree as a side effect.
__global__ void k_fill(const int* __restrict__ ei, int E, int n) {
    int e = blockIdx.x * blockDim.x + threadIdx.x;
    if (e >= E) return;
    int is64 = g_is64;
    int r = get_idx(ei, (long long)e, is64);
    int c = get_idx(ei, (long long)E + e, is64);
    if ((unsigned)r >= (unsigned)n || (unsigned)c >= (unsigned)n) return;
    int pos = atomicAdd(&g_cnt[c], 1);
    if (pos < CAP) {
        g_bucket[(size_t)c * CAP + pos] = r;
    } else {
        int o = atomicAdd(&g_ovf_cnt, 1);
        if (o < EMAX) { g_ovf_r[o] = r; g_ovf_c[o] = c; }
    }
}

// ---------------------------------------------------------------------------
// K3: dinv[i] = rsqrt(cnt[i]+1).
__global__ void k_dinv(int n) {
    int i = blockIdx.x * blockDim.x + threadIdx.x;
    if (i < n) g_dinv[i] = rsqrtf((float)(g_cnt[i] + 1));
}

// ---------------------------------------------------------------------------
// K4: y = x @ Wg. 256 nodes/block, 4-stage cp.async ring, XOR-swizzled smem
// (conflict-free LDS.128), f32x2 packed FMAs, one barrier per chunk.
__device__ __forceinline__ void cp_async16(unsigned int sa, const void* ga) {
    asm volatile("cp.async.cg.shared.global [%0], [%1], 16;" :: "r"(sa), "l"(ga));
}

// Rows are 32B (KC=8). Swizzle: float4 q of row r at r*32 + ((q ^ ((r>>2)&1))<<4)
// -> any 8 consecutive rows cover 8 distinct 16B slots per 128B window.
__device__ __forceinline__ void issue_chunk(float* xs, const float* __restrict__ x,
                                            int node0, int n, int c, int slot, int tid) {
    unsigned int sbase = (unsigned int)__cvta_generic_to_shared(xs)
                       + (unsigned int)slot * (NPB * KC * 4);
#pragma unroll
    for (int i = 0; i < 4; i++) {
        int idx = tid + i * BLK;        // 0..511
        int row = idx >> 1;             // 0..255
        int q   = idx & 1;
        int gr  = node0 + row;
        if (gr >= n) gr = n - 1;        // clamp (results discarded on write)
        const void* ga = x + (size_t)gr * 512 + c * KC + q * 4;
        unsigned int off = (unsigned int)(row * 32 + ((q ^ ((row >> 2) & 1)) << 4));
        cp_async16(sbase + off, ga);
    }
}

__global__ void __launch_bounds__(BLK, 3) k_gemm(const float* __restrict__ x,
                                                 const float* __restrict__ Wg, int n) {
    extern __shared__ float sm[];
    float* Ws = sm;             // 512*16 floats = 32KB
    float* xs = sm + 512 * 16;  // NSTG * 256 * 8 floats = 32KB

    int tid = threadIdx.x;
    int node0 = blockIdx.x * NPB;

    for (int i = tid; i < (512 * 16) / 4; i += BLK)
        reinterpret_cast<float4*>(Ws)[i] = reinterpret_cast<const float4*>(Wg)[i];

#pragma unroll
    for (int p = 0; p < NSTG - 1; p++) {
        issue_chunk(xs, x, node0, n, p, p, tid);
        asm volatile("cp.async.commit_group;" ::: "memory");
    }

    unsigned long long acc0[8], acc1[8];
#pragma unroll
    for (int j = 0; j < 8; j++) { acc0[j] = 0ull; acc1[j] = 0ull; }

    int s = (tid >> 2) & 1;  // same for rows tid and tid+128

    for (int c = 0; c < NCH; c++) {
        asm volatile("cp.async.wait_group 2;" ::: "memory");
        __syncthreads();  // chunk c visible to all; chunk c-1 consumed by all
        if (c + NSTG - 1 < NCH)
            issue_chunk(xs, x, node0, n, c + NSTG - 1, (c + NSTG - 1) & (NSTG - 1), tid);
        asm volatile("cp.async.commit_group;" ::: "memory");  // may be empty (tail)

        const float* bb = xs + (c & (NSTG - 1)) * (NPB * KC);
#pragma unroll
        for (int q = 0; q < 2; q++) {
            float4 a  = *reinterpret_cast<const float4*>(bb + tid * 8 + ((q ^ s) << 2));
            float4 b4 = *reinterpret_cast<const float4*>(bb + (tid + 128) * 8 + ((q ^ s) << 2));
            const float* xa = &a.x;
            const float* xb = &b4.x;
#pragma unroll
            for (int d = 0; d < 4; d++) {
                int k = c * KC + q * 4 + d;
                const unsigned long long* w2 =
                    reinterpret_cast<const unsigned long long*>(Ws + k * 16);
                unsigned long long xv0 = pk2(xa[d]);
                unsigned long long xv1 = pk2(xb[d]);
#pragma unroll
                for (int j = 0; j < 8; j++) {
                    acc0[j] = fma2(xv0, w2[j], acc0[j]);
                    acc1[j] = fma2(xv1, w2[j], acc1[j]);
                }
            }
        }
    }

    int i0 = node0 + tid;
    int i1 = i0 + 128;
    if (i0 < n) {
        unsigned long long* yo = reinterpret_cast<unsigned long long*>(g_y + (size_t)i0 * 16);
#pragma unroll
        for (int j = 0; j < 8; j++) yo[j] = acc0[j];
    }
    if (i1 < n) {
        unsigned long long* yo = reinterpret_cast<unsigned long long*>(g_y + (size_t)i1 * 16);
#pragma unroll
        for (int j = 0; j < 8; j++) yo[j] = acc1[j];
    }
}

// ---------------------------------------------------------------------------
// K5: per-node gather-aggregate. One warp per node; half-warps process
// alternating bucket entries, lanes 0-15/16-31 carry one feature each.
__global__ void k_agg(int n) {
    int warp = (blockIdx.x * blockDim.x + threadIdx.x) >> 5;
    int lane = threadIdx.x & 31;
    if (warp >= n) return;
    int c    = warp;
    int half = lane >> 4;
    int f    = lane & 15;

    int cnt = g_cnt[c];
    int m   = cnt < CAP ? cnt : CAP;
    const int* bk = g_bucket + (size_t)c * CAP;

    float acc = 0.f;
    int k = half;
    for (; k + 6 < m; k += 8) {
        int r0 = bk[k], r1 = bk[k + 2], r2 = bk[k + 4], r3 = bk[k + 6];
        float s0 = g_dinv[r0], s1 = g_dinv[r1], s2 = g_dinv[r2], s3 = g_dinv[r3];
        float v0 = g_y[(size_t)r0 * 16 + f];
        float v1 = g_y[(size_t)r1 * 16 + f];
        float v2 = g_y[(size_t)r2 * 16 + f];
        float v3 = g_y[(size_t)r3 * 16 + f];
        acc += v0 * s0 + v1 * s1 + v2 * s2 + v3 * s3;
    }
    for (; k < m; k += 2) {
        int r = bk[k];
        acc += g_y[(size_t)r * 16 + f] * g_dinv[r];
    }

    if (cnt > CAP) {  // rare/adversarial: scan overflow list for this node
        int oc = g_ovf_cnt; if (oc > EMAX) oc = EMAX;
        for (int i = half; i < oc; i += 2) {
            if (g_ovf_c[i] == c) {
                int r = g_ovf_r[i];
                acc += g_y[(size_t)r * 16 + f] * g_dinv[r];
            }
        }
    }

    acc += __shfl_xor_sync(0xffffffff, acc, 16);
    if (lane < 16) g_acc[(size_t)c * 16 + lane] = acc;
}

// ---------------------------------------------------------------------------
// K6: finalize GCN layer + 3-layer MLP + sigmoid.
__global__ void k_final(const float* __restrict__ bg,
                        const float* __restrict__ W1, const float* __restrict__ b1,
                        const float* __restrict__ W2, const float* __restrict__ b2,
                        const float* __restrict__ W3, const float* __restrict__ b3,
                        float* __restrict__ out, int n) {
    __shared__ float sW1[256], sW2[512], sW3[32];
    __shared__ float sbg[16], sb1[16], sb2[32], sb3;
    int t = threadIdx.x;
    if (t < 256) sW1[t] = W1[t];
    for (int q = t; q < 512; q += blockDim.x) sW2[q] = W2[q];
    if (t < 32) { sW3[t] = W3[t]; sb2[t] = b2[t]; }
    if (t < 16) { sb1[t] = b1[t]; sbg[t] = bg[t]; }
    if (t == 0) sb3 = b3[0];
    __syncthreads();

    int i = blockIdx.x * blockDim.x + t;
    if (i >= n) return;

    float di = g_dinv[i];
    const float4* ar = reinterpret_cast<const float4*>(g_acc) + (size_t)i * 4;
    const float4* yr = reinterpret_cast<const float4*>(g_y) + (size_t)i * 4;

    float h0[16];
#pragma unroll
    for (int q = 0; q < 4; q++) {
        float4 a = ar[q];
        float4 y = yr[q];
        h0[q * 4 + 0] = fmaxf((a.x + y.x * di) * di + sbg[q * 4 + 0], 0.f);
        h0[q * 4 + 1] = fmaxf((a.y + y.y * di) * di + sbg[q * 4 + 1], 0.f);
        h0[q * 4 + 2] = fmaxf((a.z + y.z * di) * di + sbg[q * 4 + 2], 0.f);
        h0[q * 4 + 3] = fmaxf((a.w + y.w * di) * di + sbg[q * 4 + 3], 0.f);
    }

    float h1[16];
#pragma unroll
    for (int j = 0; j < 16; j++) {
        float s = sb1[j];
#pragma unroll
        for (int k = 0; k < 16; k++) s += h0[k] * sW1[k * 16 + j];
        h1[j] = fmaxf(s, 0.f);
    }

    float z = sb3;
#pragma unroll
    for (int j = 0; j < 32; j++) {
        float s = sb2[j];
#pragma unroll
        for (int k = 0; k < 16; k++) s += h1[k] * sW2[k * 32 + j];
        z += fmaxf(s, 0.f) * sW3[j];
    }

    out[i] = 1.f / (1.f + expf(-z));
}

// ---------------------------------------------------------------------------
extern "C" void kernel_launch(void* const* d_in, const int* in_sizes, int n_in,
                              void* d_out, int out_size) {
    const float* x  = (const float*)d_in[0];
    const int*   ei = (const int*)d_in[1];   // edge_index words (int32 or int64 LE)
    const float* Wg = (const float*)d_in[2];
    const float* bg = (const float*)d_in[3];
    const float* W1 = (const float*)d_in[4];
    const float* b1 = (const float*)d_in[5];
    const float* W2 = (const float*)d_in[6];
    const float* b2 = (const float*)d_in[7];
    const float* W3 = (const float*)d_in[8];
    const float* b3 = (const float*)d_in[9];
    float* out = (float*)d_out;

    int n = in_sizes[0] / 512;
    int E = in_sizes[1] / 2;   // element count, dtype-independent
    if (n > NMAX) n = NMAX;
    if (E > EMAX) E = EMAX;

    static int smem_set = 0;
    int gemm_smem = (512 * 16 + NSTG * NPB * KC) * 4;  // 32KB + 32KB = 64KB
    if (!smem_set) {
        cudaFuncSetAttribute(k_gemm, cudaFuncAttributeMaxDynamicSharedMemorySize, gemm_smem);
        smem_set = 1;
    }

    k_detect<<<1, 1>>>(ei);
    k_init  <<<(n + 255) / 256, 256>>>(n);
    k_fill  <<<(E + 255) / 256, 256>>>(ei, E, n);
    k_dinv  <<<(n + 255) / 256, 256>>>(n);
    k_gemm  <<<(n + NPB - 1) / NPB, BLK, gemm_smem>>>(x, Wg, n);
    k_agg   <<<(n + 7) / 8, 256>>>(n);
    k_final <<<(n + 255) / 256, 256>>>(bg, W1, b1, W2, b2, W3, b3, out, n);
}

// round 8
// speedup vs baseline: 1.8464x; 1.2716x over previous
#include <cuda_runtime.h>
#include <cstdint>

// Problem-size upper bounds (actual sizes derived from in_sizes at launch).
#define NMAX 100000
#define EMAX 3200000
#define CAP  128     // bucket capacity per node (random E/N=32; overflow -> list)

// GEMM tiling
#define BLK   128   // threads per block
#define NPB   256   // nodes per block (2 per thread)
#define KC    8     // K-chunk (floats per row per chunk)
#define NCH   64    // 512 / KC
#define NSTG  4     // cp.async pipeline stages

// Scratch (allocation-free rule: __device__ globals).
__device__ int                  g_is64;            // edge_index dtype flag
__device__ int                  g_cnt[NMAX];       // in-degree (excl. self loop)
__device__ float                g_dinv[NMAX];      // rsqrt(cnt+1)
__device__ int                  g_bucket[(size_t)NMAX * CAP];
__device__ int                  g_ovf_cnt;
__device__ int                  g_ovf_r[EMAX];
__device__ int                  g_ovf_c[EMAX];
__device__ __align__(16) float  g_y[NMAX * 16];    // xw[i]
__device__ __align__(16) float  g_acc[NMAX * 16];  // sum_in y[r]*dinv[r]

__device__ __forceinline__ int get_idx(const int* __restrict__ ei, long long p, int is64) {
    return is64 ? ei[p * 2] : ei[p];
}

// f32x2 packed-FMA helpers (Blackwell dual-FMA pipe; PTX-only).
__device__ __forceinline__ unsigned long long pk2(float v) {
    unsigned long long r;
    asm("mov.b64 %0, {%1, %1};" : "=l"(r) : "f"(v));
    return r;
}
__device__ __forceinline__ unsigned long long fma2(unsigned long long a,
                                                   unsigned long long b,
                                                   unsigned long long c) {
    unsigned long long d;
    asm("fma.rn.f32x2 %0, %1, %2, %3;" : "=l"(d) : "l"(a), "l"(b), "l"(c));
    return d;
}

// ---------------------------------------------------------------------------
// K1: zero counters + dtype detect (thread 0).
__global__ void k_init(const int* __restrict__ ei, int n) {
    int i = blockIdx.x * blockDim.x + threadIdx.x;
    if (i < n) g_cnt[i] = 0;
    if (i == 0) {
        g_ovf_cnt = 0;
        int is64 = 1;
        for (int k = 1; k < 64; k += 2)
            if (ei[k] != 0) { is64 = 0; break; }
        g_is64 = is64;
    }
}

// ---------------------------------------------------------------------------
// K2: bucket fill. bucket[c][pos] = r; counts in-degree as a side effect.
__global__ void k_fill(const int* __restrict__ ei, int E, int n) {
    int e = blockIdx.x * blockDim.x + threadIdx.x;
    if (e >= E) return;
    int is64 = g_is64;
    int r = get_idx(ei, (long long)e, is64);
    int c = get_idx(ei, (long long)E + e, is64);
    if ((unsigned)r >= (unsigned)n || (unsigned)c >= (unsigned)n) return;
    int pos = atomicAdd(&g_cnt[c], 1);
    if (pos < CAP) {
        g_bucket[(size_t)c * CAP + pos] = r;
    } else {
        int o = atomicAdd(&g_ovf_cnt, 1);
        if (o < EMAX) { g_ovf_r[o] = r; g_ovf_c[o] = c; }
    }
}

// ---------------------------------------------------------------------------
// K3: dinv[i] = rsqrt(cnt[i]+1).
__global__ void k_dinv(int n) {
    int i = blockIdx.x * blockDim.x + threadIdx.x;
    if (i < n) g_dinv[i] = rsqrtf((float)(g_cnt[i] + 1));
}

// ---------------------------------------------------------------------------
// K4: y = x @ Wg. 256 nodes/block, 4-stage cp.async ring, XOR-swizzled smem
// (conflict-free LDS.128), f32x2 packed FMAs, one barrier per chunk.
__device__ __forceinline__ void cp_async16(unsigned int sa, const void* ga) {
    asm volatile("cp.async.cg.shared.global [%0], [%1], 16;" :: "r"(sa), "l"(ga));
}

// Rows are 32B (KC=8). Swizzle: float4 q of row r at r*32 + ((q ^ ((r>>2)&1))<<4)
// -> any 8 consecutive rows cover 8 distinct 16B slots per 128B window.
__device__ __forceinline__ void issue_chunk(float* xs, const float* __restrict__ x,
                                            int node0, int n, int c, int slot, int tid) {
    unsigned int sbase = (unsigned int)__cvta_generic_to_shared(xs)
                       + (unsigned int)slot * (NPB * KC * 4);
#pragma unroll
    for (int i = 0; i < 4; i++) {
        int idx = tid + i * BLK;        // 0..511
        int row = idx >> 1;             // 0..255
        int q   = idx & 1;
        int gr  = node0 + row;
        if (gr >= n) gr = n - 1;        // clamp (results discarded on write)
        const void* ga = x + (size_t)gr * 512 + c * KC + q * 4;
        unsigned int off = (unsigned int)(row * 32 + ((q ^ ((row >> 2) & 1)) << 4));
        cp_async16(sbase + off, ga);
    }
}

__global__ void __launch_bounds__(BLK, 3) k_gemm(const float* __restrict__ x,
                                                 const float* __restrict__ Wg, int n) {
    extern __shared__ float sm[];
    float* Ws = sm;             // 512*16 floats = 32KB
    float* xs = sm + 512 * 16;  // NSTG * 256 * 8 floats = 32KB

    int tid = threadIdx.x;
    int node0 = blockIdx.x * NPB;

    for (int i = tid; i < (512 * 16) / 4; i += BLK)
        reinterpret_cast<float4*>(Ws)[i] = reinterpret_cast<const float4*>(Wg)[i];

#pragma unroll
    for (int p = 0; p < NSTG - 1; p++) {
        issue_chunk(xs, x, node0, n, p, p, tid);
        asm volatile("cp.async.commit_group;" ::: "memory");
    }

    unsigned long long acc0[8], acc1[8];
#pragma unroll
    for (int j = 0; j < 8; j++) { acc0[j] = 0ull; acc1[j] = 0ull; }

    int s = (tid >> 2) & 1;  // same for rows tid and tid+128

    for (int c = 0; c < NCH; c++) {
        asm volatile("cp.async.wait_group 2;" ::: "memory");
        __syncthreads();  // chunk c visible to all; chunk c-1 consumed by all
        if (c + NSTG - 1 < NCH)
            issue_chunk(xs, x, node0, n, c + NSTG - 1, (c + NSTG - 1) & (NSTG - 1), tid);
        asm volatile("cp.async.commit_group;" ::: "memory");  // may be empty (tail)

        const float* bb = xs + (c & (NSTG - 1)) * (NPB * KC);
#pragma unroll
        for (int q = 0; q < 2; q++) {
            float4 a  = *reinterpret_cast<const float4*>(bb + tid * 8 + ((q ^ s) << 2));
            float4 b4 = *reinterpret_cast<const float4*>(bb + (tid + 128) * 8 + ((q ^ s) << 2));
            const float* xa = &a.x;
            const float* xb = &b4.x;
#pragma unroll
            for (int d = 0; d < 4; d++) {
                int k = c * KC + q * 4 + d;
                const unsigned long long* w2 =
                    reinterpret_cast<const unsigned long long*>(Ws + k * 16);
                unsigned long long xv0 = pk2(xa[d]);
                unsigned long long xv1 = pk2(xb[d]);
#pragma unroll
                for (int j = 0; j < 8; j++) {
                    acc0[j] = fma2(xv0, w2[j], acc0[j]);
                    acc1[j] = fma2(xv1, w2[j], acc1[j]);
                }
            }
        }
    }

    int i0 = node0 + tid;
    int i1 = i0 + 128;
    if (i0 < n) {
        unsigned long long* yo = reinterpret_cast<unsigned long long*>(g_y + (size_t)i0 * 16);
#pragma unroll
        for (int j = 0; j < 8; j++) yo[j] = acc0[j];
    }
    if (i1 < n) {
        unsigned long long* yo = reinterpret_cast<unsigned long long*>(g_y + (size_t)i1 * 16);
#pragma unroll
        for (int j = 0; j < 8; j++) yo[j] = acc1[j];
    }
}

// ---------------------------------------------------------------------------
// K5: per-node gather-aggregate. One warp per node; half-warps process
// alternating bucket entries, lanes 0-15/16-31 carry one feature each.
__global__ void k_agg(int n) {
    int warp = (blockIdx.x * blockDim.x + threadIdx.x) >> 5;
    int lane = threadIdx.x & 31;
    if (warp >= n) return;
    int c    = warp;
    int half = lane >> 4;
    int f    = lane & 15;

    int cnt = g_cnt[c];
    int m   = cnt < CAP ? cnt : CAP;
    const int* bk = g_bucket + (size_t)c * CAP;

    float acc = 0.f;
    int k = half;
    for (; k + 6 < m; k += 8) {
        int r0 = bk[k], r1 = bk[k + 2], r2 = bk[k + 4], r3 = bk[k + 6];
        float s0 = g_dinv[r0], s1 = g_dinv[r1], s2 = g_dinv[r2], s3 = g_dinv[r3];
        float v0 = g_y[(size_t)r0 * 16 + f];
        float v1 = g_y[(size_t)r1 * 16 + f];
        float v2 = g_y[(size_t)r2 * 16 + f];
        float v3 = g_y[(size_t)r3 * 16 + f];
        acc += v0 * s0 + v1 * s1 + v2 * s2 + v3 * s3;
    }
    for (; k < m; k += 2) {
        int r = bk[k];
        acc += g_y[(size_t)r * 16 + f] * g_dinv[r];
    }

    if (cnt > CAP) {  // rare/adversarial: scan overflow list for this node
        int oc = g_ovf_cnt; if (oc > EMAX) oc = EMAX;
        for (int i = half; i < oc; i += 2) {
            if (g_ovf_c[i] == c) {
                int r = g_ovf_r[i];
                acc += g_y[(size_t)r * 16 + f] * g_dinv[r];
            }
        }
    }

    acc += __shfl_xor_sync(0xffffffff, acc, 16);
    if (lane < 16) g_acc[(size_t)c * 16 + lane] = acc;
}

// ---------------------------------------------------------------------------
// K6: finalize GCN layer + 3-layer MLP + sigmoid.
__global__ void k_final(const float* __restrict__ bg,
                        const float* __restrict__ W1, const float* __restrict__ b1,
                        const float* __restrict__ W2, const float* __restrict__ b2,
                        const float* __restrict__ W3, const float* __restrict__ b3,
                        float* __restrict__ out, int n) {
    __shared__ float sW1[256], sW2[512], sW3[32];
    __shared__ float sbg[16], sb1[16], sb2[32], sb3;
    int t = threadIdx.x;
    if (t < 256) sW1[t] = W1[t];
    for (int q = t; q < 512; q += blockDim.x) sW2[q] = W2[q];
    if (t < 32) { sW3[t] = W3[t]; sb2[t] = b2[t]; }
    if (t < 16) { sb1[t] = b1[t]; sbg[t] = bg[t]; }
    if (t == 0) sb3 = b3[0];
    __syncthreads();

    int i = blockIdx.x * blockDim.x + t;
    if (i >= n) return;

    float di = g_dinv[i];
    const float4* ar = reinterpret_cast<const float4*>(g_acc) + (size_t)i * 4;
    const float4* yr = reinterpret_cast<const float4*>(g_y) + (size_t)i * 4;

    float h0[16];
#pragma unroll
    for (int q = 0; q < 4; q++) {
        float4 a = ar[q];
        float4 y = yr[q];
        h0[q * 4 + 0] = fmaxf((a.x + y.x * di) * di + sbg[q * 4 + 0], 0.f);
        h0[q * 4 + 1] = fmaxf((a.y + y.y * di) * di + sbg[q * 4 + 1], 0.f);
        h0[q * 4 + 2] = fmaxf((a.z + y.z * di) * di + sbg[q * 4 + 2], 0.f);
        h0[q * 4 + 3] = fmaxf((a.w + y.w * di) * di + sbg[q * 4 + 3], 0.f);
    }

    float h1[16];
#pragma unroll
    for (int j = 0; j < 16; j++) {
        float s = sb1[j];
#pragma unroll
        for (int k = 0; k < 16; k++) s += h0[k] * sW1[k * 16 + j];
        h1[j] = fmaxf(s, 0.f);
    }

    float z = sb3;
#pragma unroll
    for (int j = 0; j < 32; j++) {
        float s = sb2[j];
#pragma unroll
        for (int k = 0; k < 16; k++) s += h1[k] * sW2[k * 32 + j];
        z += fmaxf(s, 0.f) * sW3[j];
    }

    out[i] = 1.f / (1.f + expf(-z));
}

// ---------------------------------------------------------------------------
extern "C" void kernel_launch(void* const* d_in, const int* in_sizes, int n_in,
                              void* d_out, int out_size) {
    const float* x  = (const float*)d_in[0];
    const int*   ei = (const int*)d_in[1];   // edge_index words (int32 or int64 LE)
    const float* Wg = (const float*)d_in[2];
    const float* bg = (const float*)d_in[3];
    const float* W1 = (const float*)d_in[4];
    const float* b1 = (const float*)d_in[5];
    const float* W2 = (const float*)d_in[6];
    const float* b2 = (const float*)d_in[7];
    const float* W3 = (const float*)d_in[8];
    const float* b3 = (const float*)d_in[9];
    float* out = (float*)d_out;

    int n = in_sizes[0] / 512;
    int E = in_sizes[1] / 2;   // element count, dtype-independent
    if (n > NMAX) n = NMAX;
    if (E > EMAX) E = EMAX;

    // One-time setup on the eager correctness call (NOT during capture).
    static int inited = 0;
    static cudaStream_t s2;
    static cudaEvent_t evFork, evGemm;
    int gemm_smem = (512 * 16 + NSTG * NPB * KC) * 4;  // 64KB
    if (!inited) {
        cudaFuncSetAttribute(k_gemm, cudaFuncAttributeMaxDynamicSharedMemorySize, gemm_smem);
        cudaStreamCreateWithFlags(&s2, cudaStreamNonBlocking);
        cudaEventCreateWithFlags(&evFork, cudaEventDisableTiming);
        cudaEventCreateWithFlags(&evGemm, cudaEventDisableTiming);
        inited = 1;
    }

    // Fork: gemm (x@Wg) is independent of the edge pipeline -> run on s2.
    cudaEventRecord(evFork, 0);
    cudaStreamWaitEvent(s2, evFork, 0);
    k_gemm<<<(n + NPB - 1) / NPB, BLK, gemm_smem, s2>>>(x, Wg, n);
    cudaEventRecord(evGemm, s2);

    // Edge pipeline on the capture (NULL) stream.
    k_init<<<(n + 255) / 256, 256>>>(ei, n);
    k_fill<<<(E + 255) / 256, 256>>>(ei, E, n);
    k_dinv<<<(n + 255) / 256, 256>>>(n);

    // Join: agg needs both g_y (gemm) and buckets/dinv (edge pipeline).
    cudaStreamWaitEvent(0, evGemm, 0);
    k_agg  <<<(n + 7) / 8, 256>>>(n);
    k_final<<<(n + 255) / 256, 256>>>(bg, W1, b1, W2, b2, W3, b3, out, n);
}

// round 9
// speedup vs baseline: 1.9028x; 1.0306x over previous
#include <cuda_runtime.h>
#include <cstdint>

// Problem-size upper bounds (actual sizes derived from in_sizes at launch).
#define NMAX 100000
#define EMAX 3200000
#define CAP  128     // bucket capacity per node (random E/N=32; overflow -> list)

// GEMM tiling
#define BLK   128   // threads per block (4 warps)
#define NPB   256   // nodes per block (64 per warp, 2 per thread)
#define KC    8     // K-chunk (floats per row per chunk)
#define NCH   64    // 512 / KC
#define NSTG  4     // cp.async pipeline stages (per-warp ring)

// Scratch (allocation-free rule: __device__ globals).
__device__ int                  g_is64;            // edge_index dtype flag
__device__ int                  g_cnt[NMAX];       // in-degree (excl. self loop)
__device__ float                g_dinv[NMAX];      // rsqrt(cnt+1)
__device__ int                  g_bucket[(size_t)NMAX * CAP];
__device__ int                  g_ovf_cnt;
__device__ int                  g_ovf_r[EMAX];
__device__ int                  g_ovf_c[EMAX];
__device__ __align__(16) float  g_y[NMAX * 16];    // xw[i]
__device__ __align__(16) float  g_acc[NMAX * 16];  // sum_in y[r]*dinv[r]

__device__ __forceinline__ int get_idx(const int* __restrict__ ei, long long p, int is64) {
    return is64 ? ei[p * 2] : ei[p];
}

// f32x2 packed-FMA helpers (Blackwell dual-FMA pipe; PTX-only).
__device__ __forceinline__ unsigned long long pk2(float v) {
    unsigned long long r;
    asm("mov.b64 %0, {%1, %1};" : "=l"(r) : "f"(v));
    return r;
}
__device__ __forceinline__ unsigned long long fma2(unsigned long long a,
                                                   unsigned long long b,
                                                   unsigned long long c) {
    unsigned long long d;
    asm("fma.rn.f32x2 %0, %1, %2, %3;" : "=l"(d) : "l"(a), "l"(b), "l"(c));
    return d;
}

// ---------------------------------------------------------------------------
// K1: zero counters + dtype detect (thread 0).
__global__ void k_init(const int* __restrict__ ei, int n) {
    int i = blockIdx.x * blockDim.x + threadIdx.x;
    if (i < n) g_cnt[i] = 0;
    if (i == 0) {
        g_ovf_cnt = 0;
        int is64 = 1;
        for (int k = 1; k < 64; k += 2)
            if (ei[k] != 0) { is64 = 0; break; }
        g_is64 = is64;
    }
}

// ---------------------------------------------------------------------------
// K2: bucket fill. bucket[c][pos] = r; counts in-degree as a side effect.
__global__ void k_fill(const int* __restrict__ ei, int E, int n) {
    int e = blockIdx.x * blockDim.x + threadIdx.x;
    if (e >= E) return;
    int is64 = g_is64;
    int r = get_idx(ei, (long long)e, is64);
    int c = get_idx(ei, (long long)E + e, is64);
    if ((unsigned)r >= (unsigned)n || (unsigned)c >= (unsigned)n) return;
    int pos = atomicAdd(&g_cnt[c], 1);
    if (pos < CAP) {
        g_bucket[(size_t)c * CAP + pos] = r;
    } else {
        int o = atomicAdd(&g_ovf_cnt, 1);
        if (o < EMAX) { g_ovf_r[o] = r; g_ovf_c[o] = c; }
    }
}

// ---------------------------------------------------------------------------
// K3: dinv[i] = rsqrt(cnt[i]+1).
__global__ void k_dinv(int n) {
    int i = blockIdx.x * blockDim.x + threadIdx.x;
    if (i < n) g_dinv[i] = rsqrtf((float)(g_cnt[i] + 1));
}

// ---------------------------------------------------------------------------
// K4: y = x @ Wg. Warp-owned 64-row slices; per-warp cp.async ring (4 stages);
// NO block barriers in the mainloop (only one after the W smem load).
__device__ __forceinline__ void cp_async16(unsigned int sa, const void* ga) {
    asm volatile("cp.async.cg.shared.global [%0], [%1], 16;" :: "r"(sa), "l"(ga));
}

// Per-warp slice: 64 rows x 8 floats (32B rows). float4 q of row r stored at
// r*32 + ((q ^ ((r>>2)&1))<<4) (mild swizzle halves read conflicts).
__device__ __forceinline__ void issue_chunk_w(unsigned int sxs, const float* __restrict__ x,
                                              int gr0, int n, int c, int slot, int lane) {
    unsigned int sbase = sxs + (unsigned int)slot * (NPB * KC * 4);
#pragma unroll
    for (int i = 0; i < 4; i++) {
        int idx = lane + i * 32;        // 0..127
        int row = idx >> 1;             // 0..63
        int q   = idx & 1;
        int gr  = gr0 + row;
        if (gr >= n) gr = n - 1;        // clamp (results discarded on write)
        const void* ga = x + (size_t)gr * 512 + c * KC + q * 4;
        unsigned int off = (unsigned int)(row * 32 + ((q ^ ((row >> 2) & 1)) << 4));
        cp_async16(sbase + off, ga);
    }
    asm volatile("cp.async.commit_group;" ::: "memory");
}

__global__ void __launch_bounds__(BLK, 3) k_gemm(const float* __restrict__ x,
                                                 const float* __restrict__ Wg, int n) {
    extern __shared__ float sm[];
    float* Ws = sm;             // 512*16 floats = 32KB
    float* xs = sm + 512 * 16;  // NSTG * 256 * 8 floats = 32KB

    int tid  = threadIdx.x;
    int lane = tid & 31;
    int warp = tid >> 5;
    int node0 = blockIdx.x * NPB;
    int gr0   = node0 + warp * 64;      // this warp's first row

    // Per-warp smem slice base (bytes).
    unsigned int sxs = (unsigned int)__cvta_generic_to_shared(xs)
                     + (unsigned int)warp * (64 * KC * 4);

    // Prefetch first stages BEFORE the W barrier (cp.async doesn't touch Ws).
#pragma unroll
    for (int p = 0; p < NSTG - 1; p++)
        issue_chunk_w(sxs, x, gr0, n, p, p, lane);

    for (int i = tid; i < (512 * 16) / 4; i += BLK)
        reinterpret_cast<float4*>(Ws)[i] = reinterpret_cast<const float4*>(Wg)[i];
    __syncthreads();  // W visible; the ONLY block barrier

    unsigned long long acc0[8], acc1[8];
#pragma unroll
    for (int j = 0; j < 8; j++) { acc0[j] = 0ull; acc1[j] = 0ull; }

    int s0 = (lane >> 2) & 1;           // swizzle bit for row = lane
    // row lane+32: ((lane+32)>>2)&1 = ((lane>>2)+8)&1 -> same bit
    const float* wslice = xs + warp * (64 * KC);

    for (int c = 0; c < NCH; c++) {
        asm volatile("cp.async.wait_group 2;" ::: "memory");
        if (c + NSTG - 1 < NCH)
            issue_chunk_w(sxs, x, gr0, n, c + NSTG - 1, (c + NSTG - 1) & (NSTG - 1), lane);
        else
            asm volatile("cp.async.commit_group;" ::: "memory");  // keep group count in step

        const float* bb = wslice + (c & (NSTG - 1)) * (NPB * KC);
#pragma unroll
        for (int q = 0; q < 2; q++) {
            float4 a  = *reinterpret_cast<const float4*>(bb + lane * 8 + ((q ^ s0) << 2));
            float4 b4 = *reinterpret_cast<const float4*>(bb + (lane + 32) * 8 + ((q ^ s0) << 2));
            const float* xa = &a.x;
            const float* xb = &b4.x;
#pragma unroll
            for (int d = 0; d < 4; d++) {
                int k = c * KC + q * 4 + d;
                const ulonglong2* wp = reinterpret_cast<const ulonglong2*>(Ws + k * 16);
                ulonglong2 wA = wp[0], wB = wp[1], wC = wp[2], wD = wp[3];
                unsigned long long xv0 = pk2(xa[d]);
                unsigned long long xv1 = pk2(xb[d]);
                acc0[0] = fma2(xv0, wA.x, acc0[0]);  acc1[0] = fma2(xv1, wA.x, acc1[0]);
                acc0[1] = fma2(xv0, wA.y, acc0[1]);  acc1[1] = fma2(xv1, wA.y, acc1[1]);
                acc0[2] = fma2(xv0, wB.x, acc0[2]);  acc1[2] = fma2(xv1, wB.x, acc1[2]);
                acc0[3] = fma2(xv0, wB.y, acc0[3]);  acc1[3] = fma2(xv1, wB.y, acc1[3]);
                acc0[4] = fma2(xv0, wC.x, acc0[4]);  acc1[4] = fma2(xv1, wC.x, acc1[4]);
                acc0[5] = fma2(xv0, wC.y, acc0[5]);  acc1[5] = fma2(xv1, wC.y, acc1[5]);
                acc0[6] = fma2(xv0, wD.x, acc0[6]);  acc1[6] = fma2(xv1, wD.x, acc1[6]);
                acc0[7] = fma2(xv0, wD.y, acc0[7]);  acc1[7] = fma2(xv1, wD.y, acc1[7]);
            }
        }
    }

    int i0 = gr0 + lane;
    int i1 = i0 + 32;
    if (i0 < n) {
        unsigned long long* yo = reinterpret_cast<unsigned long long*>(g_y + (size_t)i0 * 16);
#pragma unroll
        for (int j = 0; j < 8; j++) yo[j] = acc0[j];
    }
    if (i1 < n) {
        unsigned long long* yo = reinterpret_cast<unsigned long long*>(g_y + (size_t)i1 * 16);
#pragma unroll
        for (int j = 0; j < 8; j++) yo[j] = acc1[j];
    }
}

// ---------------------------------------------------------------------------
// K5: per-node gather-aggregate. One warp per node; half-warps process
// alternating bucket entries, lanes 0-15/16-31 carry one feature each.
__global__ void k_agg(int n) {
    int warp = (blockIdx.x * blockDim.x + threadIdx.x) >> 5;
    int lane = threadIdx.x & 31;
    if (warp >= n) return;
    int c    = warp;
    int half = lane >> 4;
    int f    = lane & 15;

    int cnt = g_cnt[c];
    int m   = cnt < CAP ? cnt : CAP;
    const int* bk = g_bucket + (size_t)c * CAP;

    float acc = 0.f;
    int k = half;
    for (; k + 6 < m; k += 8) {
        int r0 = bk[k], r1 = bk[k + 2], r2 = bk[k + 4], r3 = bk[k + 6];
        float s0 = g_dinv[r0], s1 = g_dinv[r1], s2 = g_dinv[r2], s3 = g_dinv[r3];
        float v0 = g_y[(size_t)r0 * 16 + f];
        float v1 = g_y[(size_t)r1 * 16 + f];
        float v2 = g_y[(size_t)r2 * 16 + f];
        float v3 = g_y[(size_t)r3 * 16 + f];
        acc += v0 * s0 + v1 * s1 + v2 * s2 + v3 * s3;
    }
    for (; k < m; k += 2) {
        int r = bk[k];
        acc += g_y[(size_t)r * 16 + f] * g_dinv[r];
    }

    if (cnt > CAP) {  // rare/adversarial: scan overflow list for this node
        int oc = g_ovf_cnt; if (oc > EMAX) oc = EMAX;
        for (int i = half; i < oc; i += 2) {
            if (g_ovf_c[i] == c) {
                int r = g_ovf_r[i];
                acc += g_y[(size_t)r * 16 + f] * g_dinv[r];
            }
        }
    }

    acc += __shfl_xor_sync(0xffffffff, acc, 16);
    if (lane < 16) g_acc[(size_t)c * 16 + lane] = acc;
}

// ---------------------------------------------------------------------------
// K6: finalize GCN layer + 3-layer MLP + sigmoid.
__global__ void k_final(const float* __restrict__ bg,
                        const float* __restrict__ W1, const float* __restrict__ b1,
                        const float* __restrict__ W2, const float* __restrict__ b2,
                        const float* __restrict__ W3, const float* __restrict__ b3,
                        float* __restrict__ out, int n) {
    __shared__ float sW1[256], sW2[512], sW3[32];
    __shared__ float sbg[16], sb1[16], sb2[32], sb3;
    int t = threadIdx.x;
    if (t < 256) sW1[t] = W1[t];
    for (int q = t; q < 512; q += blockDim.x) sW2[q] = W2[q];
    if (t < 32) { sW3[t] = W3[t]; sb2[t] = b2[t]; }
    if (t < 16) { sb1[t] = b1[t]; sbg[t] = bg[t]; }
    if (t == 0) sb3 = b3[0];
    __syncthreads();

    int i = blockIdx.x * blockDim.x + t;
    if (i >= n) return;

    float di = g_dinv[i];
    const float4* ar = reinterpret_cast<const float4*>(g_acc) + (size_t)i * 4;
    const float4* yr = reinterpret_cast<const float4*>(g_y) + (size_t)i * 4;

    float h0[16];
#pragma unroll
    for (int q = 0; q < 4; q++) {
        float4 a = ar[q];
        float4 y = yr[q];
        h0[q * 4 + 0] = fmaxf((a.x + y.x * di) * di + sbg[q * 4 + 0], 0.f);
        h0[q * 4 + 1] = fmaxf((a.y + y.y * di) * di + sbg[q * 4 + 1], 0.f);
        h0[q * 4 + 2] = fmaxf((a.z + y.z * di) * di + sbg[q * 4 + 2], 0.f);
        h0[q * 4 + 3] = fmaxf((a.w + y.w * di) * di + sbg[q * 4 + 3], 0.f);
    }

    float h1[16];
#pragma unroll
    for (int j = 0; j < 16; j++) {
        float s = sb1[j];
#pragma unroll
        for (int k = 0; k < 16; k++) s += h0[k] * sW1[k * 16 + j];
        h1[j] = fmaxf(s, 0.f);
    }

    float z = sb3;
#pragma unroll
    for (int j = 0; j < 32; j++) {
        float s = sb2[j];
#pragma unroll
        for (int k = 0; k < 16; k++) s += h1[k] * sW2[k * 32 + j];
        z += fmaxf(s, 0.f) * sW3[j];
    }

    out[i] = 1.f / (1.f + expf(-z));
}

// ---------------------------------------------------------------------------
extern "C" void kernel_launch(void* const* d_in, const int* in_sizes, int n_in,
                              void* d_out, int out_size) {
    const float* x  = (const float*)d_in[0];
    const int*   ei = (const int*)d_in[1];   // edge_index words (int32 or int64 LE)
    const float* Wg = (const float*)d_in[2];
    const float* bg = (const float*)d_in[3];
    const float* W1 = (const float*)d_in[4];
    const float* b1 = (const float*)d_in[5];
    const float* W2 = (const float*)d_in[6];
    const float* b2 = (const float*)d_in[7];
    const float* W3 = (const float*)d_in[8];
    const float* b3 = (const float*)d_in[9];
    float* out = (float*)d_out;

    int n = in_sizes[0] / 512;
    int E = in_sizes[1] / 2;   // element count, dtype-independent
    if (n > NMAX) n = NMAX;
    if (E > EMAX) E = EMAX;

    // One-time setup on the eager correctness call (NOT during capture).
    static int inited = 0;
    static cudaStream_t s2;
    static cudaEvent_t evFork, evGemm;
    int gemm_smem = (512 * 16 + NSTG * NPB * KC) * 4;  // 64KB
    if (!inited) {
        cudaFuncSetAttribute(k_gemm, cudaFuncAttributeMaxDynamicSharedMemorySize, gemm_smem);
        cudaStreamCreateWithFlags(&s2, cudaStreamNonBlocking);
        cudaEventCreateWithFlags(&evFork, cudaEventDisableTiming);
        cudaEventCreateWithFlags(&evGemm, cudaEventDisableTiming);
        inited = 1;
    }

    // Fork: gemm (x@Wg) is independent of the edge pipeline -> run on s2.
    cudaEventRecord(evFork, 0);
    cudaStreamWaitEvent(s2, evFork, 0);
    k_gemm<<<(n + NPB - 1) / NPB, BLK, gemm_smem, s2>>>(x, Wg, n);
    cudaEventRecord(evGemm, s2);

    // Edge pipeline on the capture (NULL) stream.
    k_init<<<(n + 255) / 256, 256>>>(ei, n);
    k_fill<<<(E + 255) / 256, 256>>>(ei, E, n);
    k_dinv<<<(n + 255) / 256, 256>>>(n);

    // Join: agg needs both g_y (gemm) and buckets/dinv (edge pipeline).
    cudaStreamWaitEvent(0, evGemm, 0);
    k_agg  <<<(n + 7) / 8, 256>>>(n);
    k_final<<<(n + 255) / 256, 256>>>(bg, W1, b1, W2, b2, W3, b3, out, n);
}